// round 1
// baseline (speedup 1.0000x reference)
#include <cuda_runtime.h>
#include <cstdint>

// YOLOv7 P3 head decode: [B, A*(5+NC), H, W] -> [B, A*H*W, 5+NC]
// B=16, A=3, NC=80, H=W=80, stride=8, anchors from d_in[1].
//
// Pure transpose + elementwise transform => HBM-bound (~209 MB traffic).
// Tiled smem transpose: coalesced float4 loads (channel-major) and
// coalesced float4 stores (position-major).

constexpr int B_ = 16;
constexpr int A_ = 3;
constexpr int C_ = 85;        // 5 + 80
constexpr int H_ = 80;
constexpr int W_ = 80;
constexpr int HW = H_ * W_;   // 6400
constexpr int TILE = 32;      // positions per block
constexpr int TILES_PER_SLICE = HW / TILE;   // 200
constexpr int NSLICES = B_ * A_;             // 48
constexpr float STRIDE = 8.0f;               // 640 / 80

__device__ __forceinline__ float sigmoidf_(float v) {
    return 1.0f / (1.0f + __expf(-v));
}

__global__ __launch_bounds__(256) void yolo_head_kernel(
    const float* __restrict__ in,
    const float* __restrict__ anchors,
    float* __restrict__ out)
{
    // +1 padding column -> conflict-free on both phases
    __shared__ float tile[C_][TILE + 1];

    const int tileId = blockIdx.x;                       // 0 .. 9599
    const int slice  = tileId / TILES_PER_SLICE;         // b*A + a
    const int p0     = (tileId % TILES_PER_SLICE) * TILE;
    const int a      = slice % A_;

    const float aw = anchors[a * 2 + 0];
    const float ah = anchors[a * 2 + 1];

    const float* inBase = in + (size_t)slice * C_ * HW + p0;

    // ---- Load phase: channel-major, float4-vectorized, transform in flight.
    // 85 channels * 8 float4 per channel = 680 float4 loads.
    for (int idx = threadIdx.x; idx < C_ * (TILE / 4); idx += blockDim.x) {
        const int c = idx >> 3;          // channel 0..84
        const int p = (idx & 7) << 2;    // position-in-tile 0,4,...,28
        const float4 v4 = *reinterpret_cast<const float4*>(inBase + c * HW + p);
        float v[4] = {v4.x, v4.y, v4.z, v4.w};

        #pragma unroll
        for (int i = 0; i < 4; i++) {
            const int pos = p0 + p + i;  // linear h*W + w within the slice
            float r;
            if (c == 0) {
                r = (sigmoidf_(v[i]) + (float)(pos % W_)) * STRIDE;   // px
            } else if (c == 1) {
                r = (sigmoidf_(v[i]) + (float)(pos / W_)) * STRIDE;   // py
            } else if (c == 2) {
                r = __expf(fminf(fmaxf(v[i], -16.0f), 16.0f)) * aw;   // pw
            } else if (c == 3) {
                r = __expf(fminf(fmaxf(v[i], -16.0f), 16.0f)) * ah;   // ph
            } else {
                r = sigmoidf_(v[i]);                                  // conf / cls
            }
            tile[c][p + i] = r;
        }
    }

    __syncthreads();

    // ---- Store phase: position-major, fully contiguous.
    // Tile output region = TILE*C_ = 2720 consecutive floats, 16B-aligned
    // (p0 multiple of 32 -> p0*85 multiple of 4; base pointer 256B-aligned).
    float* outBase = out + (size_t)slice * HW * C_ + (size_t)p0 * C_;

    for (int idx = threadIdx.x; idx < (TILE * C_) / 4; idx += blockDim.x) {
        const int f = idx << 2;          // flat float offset within tile output
        int p = f / C_;
        int c = f - p * C_;
        float4 o;
        float* op = &o.x;
        #pragma unroll
        for (int i = 0; i < 4; i++) {
            op[i] = tile[c][p];
            if (++c == C_) { c = 0; ++p; }
        }
        *reinterpret_cast<float4*>(outBase + f) = o;
    }
}

extern "C" void kernel_launch(void* const* d_in, const int* in_sizes, int n_in,
                              void* d_out, int out_size) {
    const float* in      = (const float*)d_in[0];
    const float* anchors = (const float*)d_in[1];
    float* out           = (float*)d_out;

    const int nBlocks = NSLICES * TILES_PER_SLICE;   // 9600
    yolo_head_kernel<<<nBlocks, 256>>>(in, anchors, out);
}

// round 2
// speedup vs baseline: 1.3195x; 1.3195x over previous
#include <cuda_runtime.h>
#include <cstdint>

// YOLOv7 P3 head decode: [B, A*(5+NC), H, W] -> [B, A*H*W, 5+NC]
// B=16, A=3, NC=80, H=W=80, stride=8.
//
// Round-2 restructure: transform writes into smem in FINAL (position-major)
// layout, so the output phase is a pure contiguous float4 copy
// (LDS.128 + STG.128, zero address math beyond idx*16). Kills the
// per-element division/gather that made round 1 issue-bound.

constexpr int B_ = 16;
constexpr int A_ = 3;
constexpr int C_ = 85;        // 5 + 80
constexpr int H_ = 80;
constexpr int W_ = 80;
constexpr int HW = H_ * W_;   // 6400
constexpr int TILE = 32;      // positions per block
constexpr int TILES_PER_SLICE = HW / TILE;   // 200
constexpr int NSLICES = B_ * A_;             // 48
constexpr int UNITS = C_ * (TILE / 4);       // 680 float4 units (load & store)
constexpr float STRIDE = 8.0f;               // 640 / 80

__device__ __forceinline__ float sigmoidf_(float v) {
    return 1.0f / (1.0f + __expf(-v));
}

__global__ __launch_bounds__(256) void yolo_head_kernel(
    const float* __restrict__ in,
    const float* __restrict__ anchors,
    float* __restrict__ out)
{
    // Position-major: sm[p*85 + c]. Row stride 85 (odd) -> the scattered
    // STS pattern in the load phase is conflict-free; the copy-out reads
    // are linear LDS.128.
    __shared__ float sm[TILE * C_];          // 2720 floats = 10880 B

    const int tid    = threadIdx.x;
    const int tileId = blockIdx.x;                       // 0 .. 9599
    const int slice  = tileId / TILES_PER_SLICE;         // b*A + a
    const int p0     = (tileId % TILES_PER_SLICE) * TILE;
    const int a      = slice % A_;

    const float aw = anchors[a * 2 + 0];
    const float ah = anchors[a * 2 + 1];

    const float* inBase = in + (size_t)slice * C_ * HW + p0;

    // ---- Load + transform phase: channel-major coalesced float4 reads,
    // scattered (conflict-free) STS.32 into position-major smem.
    #pragma unroll
    for (int k = 0; k < 3; k++) {
        const int idx = tid + k * 256;
        if (idx < UNITS) {
            const int c = idx >> 3;          // channel 0..84
            const int p = (idx & 7) << 2;    // position-in-tile 0,4,...,28
            const float4 v4 = *reinterpret_cast<const float4*>(inBase + c * HW + p);
            float v[4] = {v4.x, v4.y, v4.z, v4.w};
            float r[4];

            if (c == 0) {
                #pragma unroll
                for (int i = 0; i < 4; i++) {
                    const int pos = p0 + p + i;
                    const int gx  = pos - (pos / W_) * W_;
                    r[i] = (sigmoidf_(v[i]) + (float)gx) * STRIDE;    // px
                }
            } else if (c == 1) {
                #pragma unroll
                for (int i = 0; i < 4; i++) {
                    const int gy = (p0 + p + i) / W_;
                    r[i] = (sigmoidf_(v[i]) + (float)gy) * STRIDE;    // py
                }
            } else if (c == 2) {
                #pragma unroll
                for (int i = 0; i < 4; i++)
                    r[i] = __expf(fminf(fmaxf(v[i], -16.0f), 16.0f)) * aw;  // pw
            } else if (c == 3) {
                #pragma unroll
                for (int i = 0; i < 4; i++)
                    r[i] = __expf(fminf(fmaxf(v[i], -16.0f), 16.0f)) * ah;  // ph
            } else {
                #pragma unroll
                for (int i = 0; i < 4; i++)
                    r[i] = sigmoidf_(v[i]);                                 // conf/cls
            }

            #pragma unroll
            for (int i = 0; i < 4; i++)
                sm[(p + i) * C_ + c] = r[i];
        }
    }

    __syncthreads();

    // ---- Store phase: pure contiguous float4 copy, smem -> gmem.
    // Tile output = 2720 consecutive floats; p0*85 is a multiple of 4, so
    // outBase is 16B-aligned.
    const float4* sm4    = reinterpret_cast<const float4*>(sm);
    float4* outBase4     = reinterpret_cast<float4*>(
        out + (size_t)slice * HW * C_ + (size_t)p0 * C_);

    #pragma unroll
    for (int k = 0; k < 3; k++) {
        const int idx = tid + k * 256;
        if (idx < UNITS)
            outBase4[idx] = sm4[idx];
    }
}

extern "C" void kernel_launch(void* const* d_in, const int* in_sizes, int n_in,
                              void* d_out, int out_size) {
    const float* in      = (const float*)d_in[0];
    const float* anchors = (const float*)d_in[1];
    float* out           = (float*)d_out;

    const int nBlocks = NSLICES * TILES_PER_SLICE;   // 9600
    yolo_head_kernel<<<nBlocks, 256>>>(in, anchors, out);
}

// round 3
// speedup vs baseline: 1.6212x; 1.2286x over previous
#include <cuda_runtime.h>
#include <cstdint>

// YOLOv7 P3 head decode: [B, A*(5+NC), H, W] -> [B, A*H*W, 5+NC]
// B=16, A=3, NC=80, H=W=80, stride=8.
//
// Round-3: latency-oriented restructure. All global loads are batched into
// registers before any dependent work (3 LDG.128 in flight per warp), the
// copy-out batches LDS before STG, iterations are specialized so only the
// tail is predicated, and streaming cache hints are used (pure streaming
// workload, no reuse).

constexpr int A_ = 3;
constexpr int C_ = 85;        // 5 + 80
constexpr int H_ = 80;
constexpr int W_ = 80;
constexpr int HW = H_ * W_;   // 6400
constexpr int TILE = 32;      // positions per block
constexpr int TILES_PER_SLICE = HW / TILE;   // 200
constexpr int NSLICES = 16 * A_;             // 48
constexpr int UNITS = C_ * (TILE / 4);       // 680 float4 units
constexpr float STRIDE = 8.0f;               // 640 / 80

__device__ __forceinline__ float sigmoidf_(float v) {
    return 1.0f / (1.0f + __expf(-v));
}

__device__ __forceinline__ float expclipf_(float v) {
    return __expf(fminf(fmaxf(v, -16.0f), 16.0f));
}

__global__ __launch_bounds__(256) void yolo_head_kernel(
    const float* __restrict__ in,
    const float* __restrict__ anchors,
    float* __restrict__ out)
{
    __shared__ float sm[TILE * C_];          // position-major, stride 85

    const int tid    = threadIdx.x;
    const int tileId = blockIdx.x;                       // 0 .. 9599
    const int slice  = tileId / TILES_PER_SLICE;         // b*A + a
    const int p0     = (tileId % TILES_PER_SLICE) * TILE;
    const int a      = slice % A_;

    const float* inBase = in + (size_t)slice * C_ * HW + p0;

    const int c0 = tid >> 3;                 // channel for k=0   (0..31)
    const int p  = (tid & 7) << 2;           // position-in-tile 0,4,...,28

    // ---- Stage ALL loads first: 3 independent LDG.128 in flight per warp.
    // k=0: idx = tid        -> c = c0        (always valid, 0..255 < 680)
    // k=1: idx = tid + 256  -> c = c0 + 32   (always valid)
    // k=2: idx = tid + 512  -> c = c0 + 64   (valid iff tid < 168)
    const bool act2 = tid < (UNITS - 512);   // tid < 168

    float4 v0 = __ldcs(reinterpret_cast<const float4*>(inBase + (size_t)c0 * HW + p));
    float4 v1 = __ldcs(reinterpret_cast<const float4*>(inBase + (size_t)(c0 + 32) * HW + p));
    float4 v2;
    if (act2)
        v2 = __ldcs(reinterpret_cast<const float4*>(inBase + (size_t)(c0 + 64) * HW + p));

    // ---- Transform + scatter (conflict-free STS.32, stride-85 rows).
    // Special channels (0..3) live entirely in k=0, warp 0.
    {
        float r[4];
        float vv[4] = {v0.x, v0.y, v0.z, v0.w};
        if (c0 >= 4) {
            #pragma unroll
            for (int i = 0; i < 4; i++) r[i] = sigmoidf_(vv[i]);
        } else if (c0 == 0) {
            #pragma unroll
            for (int i = 0; i < 4; i++) {
                const int pos = p0 + p + i;
                const int gx  = pos - (pos / W_) * W_;
                r[i] = (sigmoidf_(vv[i]) + (float)gx) * STRIDE;
            }
        } else if (c0 == 1) {
            #pragma unroll
            for (int i = 0; i < 4; i++) {
                const int gy = (p0 + p + i) / W_;
                r[i] = (sigmoidf_(vv[i]) + (float)gy) * STRIDE;
            }
        } else {
            const float an = anchors[a * 2 + (c0 - 2)];   // c0==2 -> aw, c0==3 -> ah
            #pragma unroll
            for (int i = 0; i < 4; i++) r[i] = expclipf_(vv[i]) * an;
        }
        #pragma unroll
        for (int i = 0; i < 4; i++) sm[(p + i) * C_ + c0] = r[i];
    }
    {
        float vv[4] = {v1.x, v1.y, v1.z, v1.w};
        #pragma unroll
        for (int i = 0; i < 4; i++) sm[(p + i) * C_ + (c0 + 32)] = sigmoidf_(vv[i]);
    }
    if (act2) {
        float vv[4] = {v2.x, v2.y, v2.z, v2.w};
        #pragma unroll
        for (int i = 0; i < 4; i++) sm[(p + i) * C_ + (c0 + 64)] = sigmoidf_(vv[i]);
    }

    __syncthreads();

    // ---- Copy-out: batch 3 LDS.128, then 3 STG.128 (contiguous, streaming).
    const float4* sm4 = reinterpret_cast<const float4*>(sm);
    float4* outBase4  = reinterpret_cast<float4*>(
        out + (size_t)slice * HW * C_ + (size_t)p0 * C_);

    float4 o0 = sm4[tid];
    float4 o1 = sm4[tid + 256];
    float4 o2;
    if (act2) o2 = sm4[tid + 512];

    __stcs(&outBase4[tid], o0);
    __stcs(&outBase4[tid + 256], o1);
    if (act2) __stcs(&outBase4[tid + 512], o2);
}

extern "C" void kernel_launch(void* const* d_in, const int* in_sizes, int n_in,
                              void* d_out, int out_size) {
    const float* in      = (const float*)d_in[0];
    const float* anchors = (const float*)d_in[1];
    float* out           = (float*)d_out;

    const int nBlocks = NSLICES * TILES_PER_SLICE;   // 9600
    yolo_head_kernel<<<nBlocks, 256>>>(in, anchors, out);
}